// round 6
// baseline (speedup 1.0000x reference)
#include <cuda_runtime.h>
#include <math.h>

// Problem constants (fixed by the reference: B=2, S=4096, D=768, H=12, DK=64)
#define BZ 2
#define SS 4096
#define DM 768
#define HH 12
#define DK 64
#define MROWS (BZ * SS)        // 8192
#define BHN  (BZ * HH)         // 24

// Scratch: projected q,k,v in [b,h,s,dk] layout (fp32). 25 MB each.
__device__ float g_q[BZ * HH * SS * DK];
__device__ float g_k[BZ * HH * SS * DK];
__device__ float g_v[BZ * HH * SS * DK];

// ---------------------------------------------------------------------------
// QKV projection: out[b,h,s,dk] = (X @ W + bias) * scale
// Classic 128x128x8 SGEMM, 256 threads, 8x8 microtile per thread.
// blockIdx.z selects which of the three projections this CTA computes.
// ---------------------------------------------------------------------------
#define GBM 128
#define GBN 128
#define GBK 8

__global__ __launch_bounds__(256, 2)
void qkv_gemm_kernel(const float* __restrict__ Qin, const float* __restrict__ Kin,
                     const float* __restrict__ Vin,
                     const float* __restrict__ Wq, const float* __restrict__ bq,
                     const float* __restrict__ Wk, const float* __restrict__ bk,
                     const float* __restrict__ Wv, const float* __restrict__ bv)
{
    const float* X;
    const float* W;
    const float* bias;
    float* out;
    float scale;
    if (blockIdx.z == 0)      { X = Qin; W = Wq; bias = bq; out = g_q; scale = 0.125f; }
    else if (blockIdx.z == 1) { X = Kin; W = Wk; bias = bk; out = g_k; scale = 1.0f;  }
    else                      { X = Vin; W = Wv; bias = bv; out = g_v; scale = 1.0f;  }

    __shared__ float As[GBK][GBM];   // A stored transposed: As[k][m]
    __shared__ float Bs[GBK][GBN];

    const int bx  = blockIdx.x;          // N tile (0..5)
    const int by  = blockIdx.y;          // M tile (0..63)
    const int tid = threadIdx.x;
    const int tr  = tid >> 4;            // 0..15
    const int tc  = tid & 15;            // 0..15

    float acc[8][8];
#pragma unroll
    for (int i = 0; i < 8; i++)
#pragma unroll
        for (int j = 0; j < 8; j++) acc[i][j] = 0.0f;

    // A tile load mapping: 128 rows x 8 cols; thread -> (row = tid>>1, col4 = (tid&1)*4)
    const int arow = tid >> 1;
    const int acol = (tid & 1) * 4;
    // B tile load mapping: 8 rows x 128 cols; thread -> (row = tid>>5, col4 = (tid&31)*4)
    const int brow = tid >> 5;
    const int bcol = (tid & 31) * 4;

    const float* Xg = X + (size_t)(by * GBM + arow) * DM + acol;
    const float* Wg = W + (size_t)brow * DM + bx * GBN + bcol;

    for (int k0 = 0; k0 < DM; k0 += GBK) {
        float4 a = *(const float4*)(Xg + k0);
        As[acol + 0][arow] = a.x;
        As[acol + 1][arow] = a.y;
        As[acol + 2][arow] = a.z;
        As[acol + 3][arow] = a.w;
        float4 b = *(const float4*)(Wg + (size_t)k0 * DM);
        *(float4*)&Bs[brow][bcol] = b;
        __syncthreads();

#pragma unroll
        for (int k = 0; k < GBK; k++) {
            float ar[8], br[8];
            *(float4*)&ar[0] = *(const float4*)&As[k][tr * 8];
            *(float4*)&ar[4] = *(const float4*)&As[k][tr * 8 + 4];
            *(float4*)&br[0] = *(const float4*)&Bs[k][tc * 8];
            *(float4*)&br[4] = *(const float4*)&Bs[k][tc * 8 + 4];
#pragma unroll
            for (int i = 0; i < 8; i++)
#pragma unroll
                for (int j = 0; j < 8; j++)
                    acc[i][j] += ar[i] * br[j];
        }
        __syncthreads();
    }

    // Epilogue: add bias, scale, scatter to [b,h,s,dk]
#pragma unroll
    for (int i = 0; i < 8; i++) {
        int m  = by * GBM + tr * 8 + i;
        int bb = m / SS;
        int s  = m % SS;
#pragma unroll
        for (int j = 0; j < 8; j += 4) {
            int n  = bx * GBN + tc * 8 + j;     // 8-aligned => same head for 4 cols
            int h  = n / DK;
            int dk = n % DK;
            float4 r;
            r.x = (acc[i][j + 0] + bias[n + 0]) * scale;
            r.y = (acc[i][j + 1] + bias[n + 1]) * scale;
            r.z = (acc[i][j + 2] + bias[n + 2]) * scale;
            r.w = (acc[i][j + 3] + bias[n + 3]) * scale;
            *(float4*)&out[((size_t)(bb * HH + h) * SS + s) * DK + dk] = r;
        }
    }
}

// ---------------------------------------------------------------------------
// Flash attention (fp32). One thread owns one query row: q[64], o[64] in
// registers; online softmax over 32-key tiles staged in shared memory.
// Grid: (S/128, B*H); 128 threads/CTA.
// ---------------------------------------------------------------------------
#define ATN 32   // keys per tile

__global__ __launch_bounds__(128, 2)
void attn_kernel(const float* __restrict__ mask, float* __restrict__ out)
{
    __shared__ float sK[ATN * DK];
    __shared__ float sV[ATN * DK];
    __shared__ float sAdd[ATN];

    const int bh   = blockIdx.y;            // 0..23
    const int b    = bh / HH;
    const int h    = bh % HH;
    const int qrow = blockIdx.x * 128 + threadIdx.x;

    const float* Qp    = g_q + ((size_t)bh * SS + qrow) * DK;
    const float* Kbase = g_k + (size_t)bh * SS * DK;
    const float* Vbase = g_v + (size_t)bh * SS * DK;

    float q[DK];
#pragma unroll
    for (int c = 0; c < DK; c += 4)
        *(float4*)&q[c] = *(const float4*)&Qp[c];

    float o[DK];
#pragma unroll
    for (int c = 0; c < DK; c++) o[c] = 0.0f;

    float mrow = -INFINITY;
    float l = 0.0f;

    for (int kt = 0; kt < SS; kt += ATN) {
        __syncthreads();
        // Cooperative load of K/V tiles: 2048 floats each, 128 threads * 4 float4
        const float4* Kg = (const float4*)(Kbase + (size_t)kt * DK);
        const float4* Vg = (const float4*)(Vbase + (size_t)kt * DK);
#pragma unroll
        for (int i = 0; i < 4; i++) {
            int f4 = threadIdx.x + i * 128;
            ((float4*)sK)[f4] = Kg[f4];
            ((float4*)sV)[f4] = Vg[f4];
        }
        if (threadIdx.x < ATN)
            sAdd[threadIdx.x] = (1.0f - mask[(size_t)b * SS + kt + threadIdx.x]) * -10000.0f;
        __syncthreads();

        // Scores for 32 keys, 4 at a time (4 independent FMA chains)
        float sc[ATN];
        float mnew = mrow;
#pragma unroll
        for (int j = 0; j < ATN; j += 4) {
            float d0 = 0.f, d1 = 0.f, d2 = 0.f, d3 = 0.f;
            const float* k0p = &sK[(j + 0) * DK];
            const float* k1p = &sK[(j + 1) * DK];
            const float* k2p = &sK[(j + 2) * DK];
            const float* k3p = &sK[(j + 3) * DK];
#pragma unroll
            for (int c = 0; c < DK; c += 4) {
                float4 k0 = *(const float4*)&k0p[c];
                float4 k1 = *(const float4*)&k1p[c];
                float4 k2 = *(const float4*)&k2p[c];
                float4 k3 = *(const float4*)&k3p[c];
                d0 += q[c + 0] * k0.x; d0 += q[c + 1] * k0.y; d0 += q[c + 2] * k0.z; d0 += q[c + 3] * k0.w;
                d1 += q[c + 0] * k1.x; d1 += q[c + 1] * k1.y; d1 += q[c + 2] * k1.z; d1 += q[c + 3] * k1.w;
                d2 += q[c + 0] * k2.x; d2 += q[c + 1] * k2.y; d2 += q[c + 2] * k2.z; d2 += q[c + 3] * k2.w;
                d3 += q[c + 0] * k3.x; d3 += q[c + 1] * k3.y; d3 += q[c + 2] * k3.z; d3 += q[c + 3] * k3.w;
            }
            d0 += sAdd[j + 0];
            d1 += sAdd[j + 1];
            d2 += sAdd[j + 2];
            d3 += sAdd[j + 3];
            sc[j + 0] = d0; sc[j + 1] = d1; sc[j + 2] = d2; sc[j + 3] = d3;
            mnew = fmaxf(mnew, fmaxf(fmaxf(d0, d1), fmaxf(d2, d3)));
        }

        // Online-softmax rescale of running state
        float corr = __expf(mrow - mnew);   // exp(-inf)=0 on first tile
        l *= corr;
#pragma unroll
        for (int c = 0; c < DK; c++) o[c] *= corr;

        // P*V accumulation (64 independent chains across c)
#pragma unroll
        for (int j = 0; j < ATN; j++) {
            float p = __expf(sc[j] - mnew);
            l += p;
            const float* vp = &sV[j * DK];
#pragma unroll
            for (int c = 0; c < DK; c += 4) {
                float4 v4 = *(const float4*)&vp[c];
                o[c + 0] += p * v4.x;
                o[c + 1] += p * v4.y;
                o[c + 2] += p * v4.z;
                o[c + 3] += p * v4.w;
            }
        }
        mrow = mnew;
    }

    // Normalize and write output row: out[b, s, h*64 + c]
    float inv = 1.0f / l;
    float* op = out + ((size_t)b * SS + qrow) * DM + h * DK;
#pragma unroll
    for (int c = 0; c < DK; c += 4) {
        float4 r;
        r.x = o[c + 0] * inv;
        r.y = o[c + 1] * inv;
        r.z = o[c + 2] * inv;
        r.w = o[c + 3] * inv;
        *(float4*)&op[c] = r;
    }
}

// ---------------------------------------------------------------------------
// Inputs (metadata order): query, key, value, mask, Wq, bq, Wk, bk, Wv, bv
// ---------------------------------------------------------------------------
extern "C" void kernel_launch(void* const* d_in, const int* in_sizes, int n_in,
                              void* d_out, int out_size)
{
    const float* query = (const float*)d_in[0];
    const float* key   = (const float*)d_in[1];
    const float* value = (const float*)d_in[2];
    const float* mask  = (const float*)d_in[3];
    const float* Wq    = (const float*)d_in[4];
    const float* bq    = (const float*)d_in[5];
    const float* Wk    = (const float*)d_in[6];
    const float* bk    = (const float*)d_in[7];
    const float* Wv    = (const float*)d_in[8];
    const float* bv    = (const float*)d_in[9];

    dim3 gGrid(DM / GBN, MROWS / GBM, 3);   // (6, 64, 3)
    qkv_gemm_kernel<<<gGrid, 256>>>(query, key, value, Wq, bq, Wk, bk, Wv, bv);

    dim3 aGrid(SS / 128, BHN);              // (32, 24)
    attn_kernel<<<aGrid, 128>>>(mask, (float*)d_out);
}

// round 7
// speedup vs baseline: 1.0041x; 1.0041x over previous
#include <cuda_runtime.h>
#include <math.h>

// Problem constants (fixed by the reference: B=2, S=4096, D=768, H=12, DK=64)
#define BZ 2
#define SS 4096
#define DM 768
#define HH 12
#define DK 64
#define MROWS (BZ * SS)        // 8192
#define BHN  (BZ * HH)         // 24

// Scratch: projected q,k,v in [b,h,s,dk] layout (fp32). 25 MB each.
__device__ float g_q[BZ * HH * SS * DK];
__device__ float g_k[BZ * HH * SS * DK];
__device__ float g_v[BZ * HH * SS * DK];

// ---------------------------------------------------------------------------
// QKV projection: out[b,h,s,dk] = (X @ W + bias) * scale
// Classic 128x128x8 SGEMM, 256 threads, 8x8 microtile per thread.
// blockIdx.z selects which of the three projections this CTA computes.
// ---------------------------------------------------------------------------
#define GBM 128
#define GBN 128
#define GBK 8

__global__ __launch_bounds__(256, 2)
void qkv_gemm_kernel(const float* __restrict__ Qin, const float* __restrict__ Kin,
                     const float* __restrict__ Vin,
                     const float* __restrict__ Wq, const float* __restrict__ bq,
                     const float* __restrict__ Wk, const float* __restrict__ bk,
                     const float* __restrict__ Wv, const float* __restrict__ bv)
{
    const float* X;
    const float* W;
    const float* bias;
    float* out;
    float scale;
    if (blockIdx.z == 0)      { X = Qin; W = Wq; bias = bq; out = g_q; scale = 0.125f; }
    else if (blockIdx.z == 1) { X = Kin; W = Wk; bias = bk; out = g_k; scale = 1.0f;  }
    else                      { X = Vin; W = Wv; bias = bv; out = g_v; scale = 1.0f;  }

    __shared__ float As[GBK][GBM];   // A stored transposed: As[k][m]
    __shared__ float Bs[GBK][GBN];

    const int bx  = blockIdx.x;          // N tile (0..5)
    const int by  = blockIdx.y;          // M tile (0..63)
    const int tid = threadIdx.x;
    const int tr  = tid >> 4;            // 0..15
    const int tc  = tid & 15;            // 0..15

    float acc[8][8];
#pragma unroll
    for (int i = 0; i < 8; i++)
#pragma unroll
        for (int j = 0; j < 8; j++) acc[i][j] = 0.0f;

    // A tile load mapping: 128 rows x 8 cols; thread -> (row = tid>>1, col4 = (tid&1)*4)
    const int arow = tid >> 1;
    const int acol = (tid & 1) * 4;
    // B tile load mapping: 8 rows x 128 cols; thread -> (row = tid>>5, col4 = (tid&31)*4)
    const int brow = tid >> 5;
    const int bcol = (tid & 31) * 4;

    const float* Xg = X + (size_t)(by * GBM + arow) * DM + acol;
    const float* Wg = W + (size_t)brow * DM + bx * GBN + bcol;

    for (int k0 = 0; k0 < DM; k0 += GBK) {
        float4 a = *(const float4*)(Xg + k0);
        As[acol + 0][arow] = a.x;
        As[acol + 1][arow] = a.y;
        As[acol + 2][arow] = a.z;
        As[acol + 3][arow] = a.w;
        float4 b = *(const float4*)(Wg + (size_t)k0 * DM);
        *(float4*)&Bs[brow][bcol] = b;
        __syncthreads();

#pragma unroll
        for (int k = 0; k < GBK; k++) {
            float ar[8], br[8];
            *(float4*)&ar[0] = *(const float4*)&As[k][tr * 8];
            *(float4*)&ar[4] = *(const float4*)&As[k][tr * 8 + 4];
            *(float4*)&br[0] = *(const float4*)&Bs[k][tc * 8];
            *(float4*)&br[4] = *(const float4*)&Bs[k][tc * 8 + 4];
#pragma unroll
            for (int i = 0; i < 8; i++)
#pragma unroll
                for (int j = 0; j < 8; j++)
                    acc[i][j] += ar[i] * br[j];
        }
        __syncthreads();
    }

    // Epilogue: add bias, scale, scatter to [b,h,s,dk]
#pragma unroll
    for (int i = 0; i < 8; i++) {
        int m  = by * GBM + tr * 8 + i;
        int bb = m / SS;
        int s  = m % SS;
#pragma unroll
        for (int j = 0; j < 8; j += 4) {
            int n  = bx * GBN + tc * 8 + j;     // 8-aligned => same head for 4 cols
            int h  = n / DK;
            int dk = n % DK;
            float4 r;
            r.x = (acc[i][j + 0] + bias[n + 0]) * scale;
            r.y = (acc[i][j + 1] + bias[n + 1]) * scale;
            r.z = (acc[i][j + 2] + bias[n + 2]) * scale;
            r.w = (acc[i][j + 3] + bias[n + 3]) * scale;
            *(float4*)&out[((size_t)(bb * HH + h) * SS + s) * DK + dk] = r;
        }
    }
}

// ---------------------------------------------------------------------------
// Flash attention (fp32). One thread owns one query row: q[64], o[64] in
// registers; online softmax over 32-key tiles staged in shared memory.
// Grid: (S/128, B*H); 128 threads/CTA.
// ---------------------------------------------------------------------------
#define ATN 32   // keys per tile

__global__ __launch_bounds__(128, 2)
void attn_kernel(const float* __restrict__ mask, float* __restrict__ out)
{
    __shared__ float sK[ATN * DK];
    __shared__ float sV[ATN * DK];
    __shared__ float sAdd[ATN];

    const int bh   = blockIdx.y;            // 0..23
    const int b    = bh / HH;
    const int h    = bh % HH;
    const int qrow = blockIdx.x * 128 + threadIdx.x;

    const float* Qp    = g_q + ((size_t)bh * SS + qrow) * DK;
    const float* Kbase = g_k + (size_t)bh * SS * DK;
    const float* Vbase = g_v + (size_t)bh * SS * DK;

    float q[DK];
#pragma unroll
    for (int c = 0; c < DK; c += 4)
        *(float4*)&q[c] = *(const float4*)&Qp[c];

    float o[DK];
#pragma unroll
    for (int c = 0; c < DK; c++) o[c] = 0.0f;

    float mrow = -INFINITY;
    float l = 0.0f;

    for (int kt = 0; kt < SS; kt += ATN) {
        __syncthreads();
        // Cooperative load of K/V tiles: 2048 floats each, 128 threads * 4 float4
        const float4* Kg = (const float4*)(Kbase + (size_t)kt * DK);
        const float4* Vg = (const float4*)(Vbase + (size_t)kt * DK);
#pragma unroll
        for (int i = 0; i < 4; i++) {
            int f4 = threadIdx.x + i * 128;
            ((float4*)sK)[f4] = Kg[f4];
            ((float4*)sV)[f4] = Vg[f4];
        }
        if (threadIdx.x < ATN)
            sAdd[threadIdx.x] = (1.0f - mask[(size_t)b * SS + kt + threadIdx.x]) * -10000.0f;
        __syncthreads();

        // Scores for 32 keys, 4 at a time (4 independent FMA chains)
        float sc[ATN];
        float mnew = mrow;
#pragma unroll
        for (int j = 0; j < ATN; j += 4) {
            float d0 = 0.f, d1 = 0.f, d2 = 0.f, d3 = 0.f;
            const float* k0p = &sK[(j + 0) * DK];
            const float* k1p = &sK[(j + 1) * DK];
            const float* k2p = &sK[(j + 2) * DK];
            const float* k3p = &sK[(j + 3) * DK];
#pragma unroll
            for (int c = 0; c < DK; c += 4) {
                float4 k0 = *(const float4*)&k0p[c];
                float4 k1 = *(const float4*)&k1p[c];
                float4 k2 = *(const float4*)&k2p[c];
                float4 k3 = *(const float4*)&k3p[c];
                d0 += q[c + 0] * k0.x; d0 += q[c + 1] * k0.y; d0 += q[c + 2] * k0.z; d0 += q[c + 3] * k0.w;
                d1 += q[c + 0] * k1.x; d1 += q[c + 1] * k1.y; d1 += q[c + 2] * k1.z; d1 += q[c + 3] * k1.w;
                d2 += q[c + 0] * k2.x; d2 += q[c + 1] * k2.y; d2 += q[c + 2] * k2.z; d2 += q[c + 3] * k2.w;
                d3 += q[c + 0] * k3.x; d3 += q[c + 1] * k3.y; d3 += q[c + 2] * k3.z; d3 += q[c + 3] * k3.w;
            }
            d0 += sAdd[j + 0];
            d1 += sAdd[j + 1];
            d2 += sAdd[j + 2];
            d3 += sAdd[j + 3];
            sc[j + 0] = d0; sc[j + 1] = d1; sc[j + 2] = d2; sc[j + 3] = d3;
            mnew = fmaxf(mnew, fmaxf(fmaxf(d0, d1), fmaxf(d2, d3)));
        }

        // Online-softmax rescale of running state
        float corr = __expf(mrow - mnew);   // exp(-inf)=0 on first tile
        l *= corr;
#pragma unroll
        for (int c = 0; c < DK; c++) o[c] *= corr;

        // P*V accumulation (64 independent chains across c)
#pragma unroll
        for (int j = 0; j < ATN; j++) {
            float p = __expf(sc[j] - mnew);
            l += p;
            const float* vp = &sV[j * DK];
#pragma unroll
            for (int c = 0; c < DK; c += 4) {
                float4 v4 = *(const float4*)&vp[c];
                o[c + 0] += p * v4.x;
                o[c + 1] += p * v4.y;
                o[c + 2] += p * v4.z;
                o[c + 3] += p * v4.w;
            }
        }
        mrow = mnew;
    }

    // Normalize and write output row: out[b, s, h*64 + c]
    float inv = 1.0f / l;
    float* op = out + ((size_t)b * SS + qrow) * DM + h * DK;
#pragma unroll
    for (int c = 0; c < DK; c += 4) {
        float4 r;
        r.x = o[c + 0] * inv;
        r.y = o[c + 1] * inv;
        r.z = o[c + 2] * inv;
        r.w = o[c + 3] * inv;
        *(float4*)&op[c] = r;
    }
}

// ---------------------------------------------------------------------------
// Inputs (metadata order): query, key, value, mask, Wq, bq, Wk, bk, Wv, bv
// ---------------------------------------------------------------------------
extern "C" void kernel_launch(void* const* d_in, const int* in_sizes, int n_in,
                              void* d_out, int out_size)
{
    const float* query = (const float*)d_in[0];
    const float* key   = (const float*)d_in[1];
    const float* value = (const float*)d_in[2];
    const float* mask  = (const float*)d_in[3];
    const float* Wq    = (const float*)d_in[4];
    const float* bq    = (const float*)d_in[5];
    const float* Wk    = (const float*)d_in[6];
    const float* bk    = (const float*)d_in[7];
    const float* Wv    = (const float*)d_in[8];
    const float* bv    = (const float*)d_in[9];

    dim3 gGrid(DM / GBN, MROWS / GBM, 3);   // (6, 64, 3)
    qkv_gemm_kernel<<<gGrid, 256>>>(query, key, value, Wq, bq, Wk, bk, Wv, bv);

    dim3 aGrid(SS / 128, BHN);              // (32, 24)
    attn_kernel<<<aGrid, 128>>>(mask, (float*)d_out);
}